// round 2
// baseline (speedup 1.0000x reference)
#include <cuda_runtime.h>

// SigNet: depth-4 path signature (C=8 incl. time) + linear head.
// K1: segmented Chen scan, f32x2-packed, in-CTA tree combine.
// K2: split-k GEMM with f32x2 k-pair packing.  K3: reduce + bias.

#define NB      128
#define SLEN    1024
#define SEG     256           // steps per segment (4 segments per batch)
#define CIN     7
#define SIGCH   4680          // 8 + 64 + 512 + 4096
#define YSTRIDE 4704
#define DOUT    256
#define KSPLIT  7
#define KCHUNK  672

typedef unsigned long long u64;

__device__ __forceinline__ u64 fma2(u64 a, u64 b, u64 c){ u64 d; asm("fma.rn.f32x2 %0,%1,%2,%3;" : "=l"(d) : "l"(a),"l"(b),"l"(c)); return d; }
__device__ __forceinline__ u64 mul2(u64 a, u64 b){ u64 d; asm("mul.rn.f32x2 %0,%1,%2;" : "=l"(d) : "l"(a),"l"(b)); return d; }
__device__ __forceinline__ u64 add2(u64 a, u64 b){ u64 d; asm("add.rn.f32x2 %0,%1,%2;" : "=l"(d) : "l"(a),"l"(b)); return d; }
__device__ __forceinline__ u64 pack2(float x, float y){ u64 d; asm("mov.b64 %0,{%1,%2};" : "=l"(d) : "f"(x),"f"(y)); return d; }
__device__ __forceinline__ float2 unpack2(u64 a){ float2 f; asm("mov.b64 {%0,%1},%2;" : "=f"(f.x),"=f"(f.y) : "l"(a)); return f; }

__device__ float g_y[NB * YSTRIDE];
__device__ float g_part[KSPLIT * NB * DOUT];

// smem float-offsets
#define OFF_VS    0            // [1024][8]
#define OFF_VDUP  8192         // [1024][16]
#define OFF_T     24576        // [4][4680]
#define SMEM_FLOATS (OFF_T + 4*SIGCH)   // 43296 floats = 173184 B

// Chen combine X = A o B  (A earlier in time). 256 threads cooperate.
__device__ __forceinline__ void chen_combine(const float* __restrict__ A,
                                             const float* __restrict__ B,
                                             float* __restrict__ X, int tid)
{
#pragma unroll
    for (int i = 0; i < 16; i++) {            // level 4: 4096
        int e  = tid + 256 * i;
        int r3 = e >> 3;                      // abc
        int r2 = e >> 6;                      // ab
        int aI = e >> 9;
        int dI = e & 7;
        float v = A[584 + e] + B[584 + e];
        v = fmaf(A[aI],      B[72 + (e & 511)], v);
        v = fmaf(A[8 + r2],  B[8  + (e & 63)],  v);
        v = fmaf(A[72 + r3], B[dI],             v);
        X[584 + e] = v;
    }
#pragma unroll
    for (int i = 0; i < 2; i++) {             // level 3: 512
        int e  = tid + 256 * i;
        int r2 = e >> 3;
        int cI = e & 7;
        float v = A[72 + e] + B[72 + e];
        v = fmaf(A[e >> 6], B[8 + (e & 63)], v);
        v = fmaf(A[8 + r2], B[cI],           v);
        X[72 + e] = v;
    }
    if (tid < 64) X[8 + tid] = A[8 + tid] + B[8 + tid] + A[tid >> 3] * B[tid & 7];
    if (tid < 8)  X[tid] = A[tid] + B[tid];
}

// ---------------------------------------------------------------------------
// Kernel 1: segmented signature scan. 1 CTA/batch, 256 threads = 4 groups x 64.
// Group g scans steps [256g, 256g+256). Thread u=tid&63 owns (a,b)=(u>>3,u&7),
// all 8 c packed as 4 f32x2 pairs, all 8 d.  State fully in registers.
// ---------------------------------------------------------------------------
__global__ __launch_bounds__(256, 1) void sig_scan_kernel(const float* __restrict__ inp)
{
    extern __shared__ float sm[];
    const int b   = blockIdx.x;
    const int tid = threadIdx.x;

    // Build increments (normal + duplicated layouts).
    const float dt = 1.0f / 1023.0f;
    const float* x = inp + (size_t)b * SLEN * CIN;
    for (int i = tid; i < SLEN * CIN; i += 256) {
        int t = i / CIN, c = i - t * CIN;
        float cur  = x[i];
        float prev = (t == 0) ? 0.0f : x[i - CIN];
        float d = cur - prev;
        sm[OFF_VS + t * 8 + c + 1] = d;
        sm[OFF_VDUP + t * 16 + 2 * (c + 1)]     = d;
        sm[OFF_VDUP + t * 16 + 2 * (c + 1) + 1] = d;
    }
    for (int t = tid; t < SLEN; t += 256) {
        float d = (t == 0) ? 0.0f : dt;
        sm[OFF_VS + t * 8]       = d;
        sm[OFF_VDUP + t * 16]     = d;
        sm[OFF_VDUP + t * 16 + 1] = d;
    }
    __syncthreads();

    const int g  = tid >> 6;
    const int u  = tid & 63;
    const int a  = u >> 3;
    const int bb = u & 7;

    u64 s1 = 0ull, s2 = 0ull;
    u64 s3[4] = {0ull, 0ull, 0ull, 0ull};
    u64 sig4[32];
#pragma unroll
    for (int i = 0; i < 32; i++) sig4[i] = 0ull;

    const u64 C24 = pack2(1.0f/24.0f, 1.0f/24.0f);
    const u64 C6  = pack2(1.0f/6.0f,  1.0f/6.0f);
    const u64 CH  = pack2(0.5f, 0.5f);

    const int t0 = g * SEG, t1 = t0 + SEG;
#pragma unroll 1
    for (int t = t0; t < t1; t++) {
        const u64* vsr = (const u64*)&sm[OFF_VS + t * 8];     // (v0,v1)(v2,v3)(v4,v5)(v6,v7)
        const u64* vdr = (const u64*)&sm[OFF_VDUP + t * 16];  // (v0,v0)...(v7,v7)
        u64 vc0 = vsr[0], vc1 = vsr[1], vc2v = vsr[2], vc3 = vsr[3];
        u64 w0=vdr[0], w1=vdr[1], w2=vdr[2], w3=vdr[3], w4=vdr[4], w5=vdr[5], w6=vdr[6], w7=vdr[7];
        u64 va2 = vdr[a];
        u64 vb2 = vdr[bb];

        u64 t6  = fma2(s1, C6, mul2(va2, C24));
        u64 uu  = fma2(s1, CH, mul2(va2, C6));
        u64 s2h = mul2(s2, CH);

        u64 vcp[4] = {vc0, vc1, vc2v, vc3};
        u64 K[4];
#pragma unroll
        for (int p = 0; p < 4; p++) {
            u64 vbc = mul2(vb2, vcp[p]);
            u64 k   = fma2(vbc, t6, s3[p]);
            K[p]    = fma2(s2h, vcp[p], k);
            s3[p]   = fma2(vbc, uu, s3[p]);
            s3[p]   = fma2(s2,  vcp[p], s3[p]);
        }
#pragma unroll
        for (int p = 0; p < 4; p++) {
            sig4[p*8+0] = fma2(K[p], w0, sig4[p*8+0]);
            sig4[p*8+1] = fma2(K[p], w1, sig4[p*8+1]);
            sig4[p*8+2] = fma2(K[p], w2, sig4[p*8+2]);
            sig4[p*8+3] = fma2(K[p], w3, sig4[p*8+3]);
            sig4[p*8+4] = fma2(K[p], w4, sig4[p*8+4]);
            sig4[p*8+5] = fma2(K[p], w5, sig4[p*8+5]);
            sig4[p*8+6] = fma2(K[p], w6, sig4[p*8+6]);
            sig4[p*8+7] = fma2(K[p], w7, sig4[p*8+7]);
        }
        u64 wab = mul2(va2, vb2);
        s2 = fma2(wab, CH, s2);
        s2 = fma2(s1, vb2, s2);
        s1 = add2(s1, va2);
    }

    // Write segment signature to T[g]
    float* P = sm + OFF_T + g * SIGCH;
#pragma unroll
    for (int p = 0; p < 4; p++) {
#pragma unroll
        for (int d = 0; d < 8; d++) {
            float2 f = unpack2(sig4[p*8+d]);
            P[584 + u * 64 + (2*p)   * 8 + d] = f.x;
            P[584 + u * 64 + (2*p+1) * 8 + d] = f.y;
        }
        float2 f3 = unpack2(s3[p]);
        P[72 + u * 8 + 2*p]     = f3.x;
        P[72 + u * 8 + 2*p + 1] = f3.y;
    }
    P[8 + u] = unpack2(s2).x;
    if (bb == 0) P[a] = unpack2(s1).x;
    __syncthreads();

    // Tree combine: U = T0 o T1, V = T2 o T3 (into vs/vdup region, now dead)
    float* U = sm;                 // 4680 floats
    float* V = sm + SIGCH;         // 4680 floats
    const float* T0 = sm + OFF_T;
    const float* T1 = sm + OFF_T + SIGCH;
    const float* T2 = sm + OFF_T + 2 * SIGCH;
    const float* T3 = sm + OFF_T + 3 * SIGCH;
    chen_combine(T0, T1, U, tid);
    chen_combine(T2, T3, V, tid);
    __syncthreads();

    // Final: S = U o V straight to global
    float* y = g_y + (size_t)b * YSTRIDE;
    chen_combine(U, V, y, tid);
    if (tid < YSTRIDE - SIGCH) y[SIGCH + tid] = 0.0f;
}

// ---------------------------------------------------------------------------
// Kernel 2: split-k GEMM partials, f32x2 packed over k-pairs.
// grid = (16 col-groups, KSPLIT), 256 threads: 128 rows x 16 cols per CTA.
// ---------------------------------------------------------------------------
__global__ __launch_bounds__(256, 1) void gemm_part_kernel(const float* __restrict__ W)
{
    __shared__ float ys[128][36];
    __shared__ float ws[16][36];

    const int tid = threadIdx.x;
    const int cg = blockIdx.x;
    const int sp = blockIdx.y;
    const int kbase = sp * KCHUNK;

    const int cp = tid & 7;
    const int rg = tid >> 3;

    u64 a00=0,a01=0,a02=0,a03=0,a10=0,a11=0,a12=0,a13=0;

    for (int kc = 0; kc < KCHUNK; kc += 32) {
        const int k0 = kbase + kc;
#pragma unroll
        for (int ii = 0; ii < 4; ii++) {
            int lin = tid + 256 * ii;
            int r = lin >> 3, seg = lin & 7;
            float4 val = *(const float4*)&g_y[r * YSTRIDE + k0 + seg * 4];
            *(float4*)&ys[r][seg * 4] = val;
        }
#pragma unroll
        for (int ii = 0; ii < 2; ii++) {
            int lin = tid + 256 * ii;
            int r = lin >> 5, cc = lin & 31;
            int k = k0 + cc;
            ws[r][cc] = (k < SIGCH) ? W[(cg * 16 + r) * SIGCH + k] : 0.0f;
        }
        __syncthreads();
#pragma unroll
        for (int kk = 0; kk < 32; kk += 4) {
            const u64* w0p = (const u64*)&ws[2*cp][kk];
            const u64* w1p = (const u64*)&ws[2*cp+1][kk];
            u64 w0a = w0p[0], w0b = w0p[1];
            u64 w1a = w1p[0], w1b = w1p[1];
            const u64* y0p = (const u64*)&ys[rg][kk];
            const u64* y1p = (const u64*)&ys[rg+32][kk];
            const u64* y2p = (const u64*)&ys[rg+64][kk];
            const u64* y3p = (const u64*)&ys[rg+96][kk];
            u64 y0a=y0p[0], y0b=y0p[1], y1a=y1p[0], y1b=y1p[1];
            u64 y2a=y2p[0], y2b=y2p[1], y3a=y3p[0], y3b=y3p[1];
            a00 = fma2(y0a,w0a,a00); a00 = fma2(y0b,w0b,a00);
            a01 = fma2(y1a,w0a,a01); a01 = fma2(y1b,w0b,a01);
            a02 = fma2(y2a,w0a,a02); a02 = fma2(y2b,w0b,a02);
            a03 = fma2(y3a,w0a,a03); a03 = fma2(y3b,w0b,a03);
            a10 = fma2(y0a,w1a,a10); a10 = fma2(y0b,w1b,a10);
            a11 = fma2(y1a,w1a,a11); a11 = fma2(y1b,w1b,a11);
            a12 = fma2(y2a,w1a,a12); a12 = fma2(y2b,w1b,a12);
            a13 = fma2(y3a,w1a,a13); a13 = fma2(y3b,w1b,a13);
        }
        __syncthreads();
    }

    const int col0 = cg * 16 + 2 * cp;
    float* p = g_part + (size_t)sp * NB * DOUT;
    float2 f;
    f = unpack2(a00); p[(rg +  0) * DOUT + col0]     = f.x + f.y;
    f = unpack2(a01); p[(rg + 32) * DOUT + col0]     = f.x + f.y;
    f = unpack2(a02); p[(rg + 64) * DOUT + col0]     = f.x + f.y;
    f = unpack2(a03); p[(rg + 96) * DOUT + col0]     = f.x + f.y;
    f = unpack2(a10); p[(rg +  0) * DOUT + col0 + 1] = f.x + f.y;
    f = unpack2(a11); p[(rg + 32) * DOUT + col0 + 1] = f.x + f.y;
    f = unpack2(a12); p[(rg + 64) * DOUT + col0 + 1] = f.x + f.y;
    f = unpack2(a13); p[(rg + 96) * DOUT + col0 + 1] = f.x + f.y;
}

// ---------------------------------------------------------------------------
__global__ void reduce_bias_kernel(const float* __restrict__ bias, float* __restrict__ out)
{
    int idx = blockIdx.x * 256 + threadIdx.x;
    float v = bias[idx & (DOUT - 1)];
#pragma unroll
    for (int s = 0; s < KSPLIT; s++)
        v += g_part[s * NB * DOUT + idx];
    out[idx] = v;
}

// ---------------------------------------------------------------------------
extern "C" void kernel_launch(void* const* d_in, const int* in_sizes, int n_in,
                              void* d_out, int out_size)
{
    (void)in_sizes; (void)n_in; (void)out_size;
    const float* inp  = (const float*)d_in[0];
    const float* W    = (const float*)d_in[1];
    const float* bias = (const float*)d_in[2];
    float* out = (float*)d_out;

    const int smem_bytes = SMEM_FLOATS * sizeof(float);   // 173184
    cudaFuncSetAttribute(sig_scan_kernel,
                         cudaFuncAttributeMaxDynamicSharedMemorySize, smem_bytes);

    sig_scan_kernel<<<NB, 256, smem_bytes>>>(inp);
    dim3 g2(16, KSPLIT);
    gemm_part_kernel<<<g2, 256>>>(W);
    reduce_bias_kernel<<<NB, 256>>>(bias, out);
}